// round 6
// baseline (speedup 1.0000x reference)
#include <cuda_runtime.h>
#include <cuda_fp16.h>
#include <cstdint>

#define B_   4
#define N_   50000
#define F_   64
#define E_   800000
#define ROWS_TOTAL (B_ * N_)          // 200000
#define E2_  (2 * E_)                 // 1600000
#define N2_  (2 * N_)                 // 100000
#define SCAN_THREADS 1024
#define SCAN_CHUNK   104              // ints per thread (26 int4)
#define N2P_ (SCAN_THREADS * SCAN_CHUNK)   // 106496 padded

// ---------------------------------------------------------------------------
// Static device scratch
// ---------------------------------------------------------------------------
// pre-activations fp16, layout [support][b*N+n][32 half2]  (51.2 MB) — R3 layout
__device__ __half2 g_preh[2ull * ROWS_TOTAL * 32];
__device__ int     g_count[N2P_];
__device__ int     g_offs[N2P_];
__device__ int     g_cursor[N2P_];
__device__ int2    g_csr_cv[E2_];     // packed (col, val-bits)

// ---------------------------------------------------------------------------
// zero counters
// ---------------------------------------------------------------------------
__global__ void zero_kernel() {
    int i = blockIdx.x * blockDim.x + threadIdx.x;
    if (i < N2P_ / 4) ((int4*)g_count)[i] = make_int4(0, 0, 0, 0);
}

// ---------------------------------------------------------------------------
// histogram of destination rows, both supports
// ---------------------------------------------------------------------------
__global__ __launch_bounds__(256) void hist_kernel(const int* __restrict__ rows1,
                                                   const int* __restrict__ rows2) {
    int t = blockIdx.x * blockDim.x + threadIdx.x;
    if (t >= E2_) return;
    int idx = (t < E_) ? __ldg(rows1 + t) : (N_ + __ldg(rows2 + (t - E_)));
    atomicAdd(&g_count[idx], 1);
}

// ---------------------------------------------------------------------------
// Single-block exclusive scan of g_count -> g_offs and g_cursor.
// ---------------------------------------------------------------------------
__global__ __launch_bounds__(SCAN_THREADS) void scan_kernel() {
    __shared__ int sm[SCAN_THREADS];
    int t = threadIdx.x;
    const int4* cnt4 = (const int4*)g_count;

    int s = 0;
#pragma unroll
    for (int j = 0; j < SCAN_CHUNK / 4; j++) {
        int4 v = cnt4[t * (SCAN_CHUNK / 4) + j];
        s += v.x + v.y + v.z + v.w;
    }
    sm[t] = s;
    __syncthreads();
#pragma unroll
    for (int off = 1; off < SCAN_THREADS; off <<= 1) {
        int add = (t >= off) ? sm[t - off] : 0;
        __syncthreads();
        sm[t] += add;
        __syncthreads();
    }
    int run = sm[t] - s;

    int4* offs4 = (int4*)g_offs;
    int4* curs4 = (int4*)g_cursor;
#pragma unroll
    for (int j = 0; j < SCAN_CHUNK / 4; j++) {
        int4 v = cnt4[t * (SCAN_CHUNK / 4) + j];
        int4 o;
        o.x = run;
        o.y = o.x + v.x;
        o.z = o.y + v.y;
        o.w = o.z + v.z;
        run  = o.w + v.w;
        offs4[t * (SCAN_CHUNK / 4) + j] = o;
        curs4[t * (SCAN_CHUNK / 4) + j] = o;
    }
}

// ---------------------------------------------------------------------------
// scatter edges into CSR slots (packed col+val)
// ---------------------------------------------------------------------------
__global__ __launch_bounds__(256) void fill_kernel(const int* __restrict__ rows1,
                                                   const int* __restrict__ cols1,
                                                   const float* __restrict__ vals1,
                                                   const int* __restrict__ rows2,
                                                   const int* __restrict__ cols2,
                                                   const float* __restrict__ vals2) {
    int t = blockIdx.x * blockDim.x + threadIdx.x;
    if (t >= E2_) return;
    int c; float v; int idx;
    if (t < E_) {
        idx = __ldg(rows1 + t);
        c   = __ldg(cols1 + t);
        v   = __ldg(vals1 + t);
    } else {
        int e = t - E_;
        idx = N_ + __ldg(rows2 + e);
        c   = __ldg(cols2 + e);
        v   = __ldg(vals2 + e);
    }
    int slot = atomicAdd(&g_cursor[idx], 1);
    g_csr_cv[slot] = make_int2(c, __float_as_int(v));
}

// ---------------------------------------------------------------------------
// pre = x@W (both supports), packed fma.rn.f32x2, fp16 out, R3 layout.
// 32 rows/block, 256 threads: (fpair = tid&31, rg = tid>>5), 4 rows/thread.
// ---------------------------------------------------------------------------
__global__ __launch_bounds__(256) void gemm_kernel(const float* __restrict__ x,
                                                   const float* __restrict__ W1,
                                                   const float* __restrict__ W2) {
    __shared__ float W1s[64 * 64];
    __shared__ float W2s[64 * 64];
    __shared__ float xs[64][33];

    int tid = threadIdx.x;
    for (int i = tid; i < 64 * 64; i += 256) {
        W1s[i] = W1[i];
        W2s[i] = W2[i];
    }
    int row0 = blockIdx.x * 32;
    const float4* xg = (const float4*)(x + (size_t)row0 * F_);
    for (int i = tid; i < 512; i += 256) {
        float4 v = xg[i];
        int r = i >> 4;
        int k = (i & 15) * 4;
        xs[k][r] = v.x; xs[k + 1][r] = v.y; xs[k + 2][r] = v.z; xs[k + 3][r] = v.w;
    }
    __syncthreads();

    int fpair = tid & 31;
    int rg    = tid >> 5;

    unsigned long long a1[4] = {0ull, 0ull, 0ull, 0ull};
    unsigned long long a2[4] = {0ull, 0ull, 0ull, 0ull};

#pragma unroll
    for (int k = 0; k < 64; k++) {
        unsigned long long w1p = *(const unsigned long long*)&W1s[k * 64 + fpair * 2];
        unsigned long long w2p = *(const unsigned long long*)&W2s[k * 64 + fpair * 2];
#pragma unroll
        for (int r = 0; r < 4; r++) {
            float xv = xs[k][rg * 4 + r];
            unsigned long long xp;
            asm("mov.b64 %0, {%1, %1};" : "=l"(xp) : "f"(xv));
            asm("fma.rn.f32x2 %0, %1, %2, %0;" : "+l"(a1[r]) : "l"(xp), "l"(w1p));
            asm("fma.rn.f32x2 %0, %1, %2, %0;" : "+l"(a2[r]) : "l"(xp), "l"(w2p));
        }
    }

    const size_t sup_stride = (size_t)ROWS_TOTAL * 32;
#pragma unroll
    for (int r = 0; r < 4; r++) {
        size_t row = (size_t)(row0 + rg * 4 + r);
        float lo, hi;
        asm("mov.b64 {%0, %1}, %2;" : "=f"(lo), "=f"(hi) : "l"(a1[r]));
        g_preh[row * 32 + fpair] = __floats2half2_rn(lo, hi);
        asm("mov.b64 {%0, %1}, %2;" : "=f"(lo), "=f"(hi) : "l"(a2[r]));
        g_preh[sup_stride + row * 32 + fpair] = __floats2half2_rn(lo, hi);
    }
}

// ---------------------------------------------------------------------------
// Gather SpMM + bias + relu. One warp per row, all 4 batches (R3 structure).
// Adds: cv-chunk prefetch (hides chunk-load L2 latency) and 2-edge unroll
// with all 8 loads issued before the FMAs (MLP ~8).
// ---------------------------------------------------------------------------
__global__ __launch_bounds__(256) void gather_kernel(const float* __restrict__ bias,
                                                     float* __restrict__ out) {
    int row  = (blockIdx.x * blockDim.x + threadIdx.x) >> 5;
    int lane = threadIdx.x & 31;
    if (row >= N_) return;

    float bx = __ldg(bias + lane * 2);
    float by = __ldg(bias + lane * 2 + 1);
    float2 acc[4];
#pragma unroll
    for (int b = 0; b < 4; b++) acc[b] = make_float2(bx, by);

    const size_t sup_stride = (size_t)ROWS_TOTAL * 32;
    const size_t bstride    = (size_t)N_ * 32;

#pragma unroll
    for (int s = 0; s < 2; s++) {
        int idx   = s * N_ + row;
        int start = g_offs[idx];
        int deg   = g_count[idx];
        const __half2* pre = g_preh + (size_t)s * sup_stride;

        // prefetch first cv chunk
        int2 cv = make_int2(0, 0);
        if (deg > 0 && lane < min(32, deg))
            cv = __ldg(g_csr_cv + start + lane);

        for (int c0 = 0; c0 < deg; c0 += 32) {
            int nc = min(32, deg - c0);
            int2 cur = cv;
            // prefetch next chunk while we chew on this one
            int nxt = c0 + 32;
            if (nxt < deg) {
                cv = make_int2(0, 0);
                if (lane < min(32, deg - nxt))
                    cv = __ldg(g_csr_cv + start + nxt + lane);
            }

            int i = 0;
            for (; i + 2 <= nc; i += 2) {
                int   ci0 = __shfl_sync(0xffffffffu, cur.x, i);
                float vi0 = __int_as_float(__shfl_sync(0xffffffffu, cur.y, i));
                int   ci1 = __shfl_sync(0xffffffffu, cur.x, i + 1);
                float vi1 = __int_as_float(__shfl_sync(0xffffffffu, cur.y, i + 1));
                const __half2* s0 = pre + (size_t)ci0 * 32 + lane;
                const __half2* s1 = pre + (size_t)ci1 * 32 + lane;
                __half2 h00 = __ldg(s0);
                __half2 h01 = __ldg(s0 + bstride);
                __half2 h02 = __ldg(s0 + 2 * bstride);
                __half2 h03 = __ldg(s0 + 3 * bstride);
                __half2 h10 = __ldg(s1);
                __half2 h11 = __ldg(s1 + bstride);
                __half2 h12 = __ldg(s1 + 2 * bstride);
                __half2 h13 = __ldg(s1 + 3 * bstride);
                float2 f;
                f = __half22float2(h00); acc[0].x = fmaf(vi0, f.x, acc[0].x); acc[0].y = fmaf(vi0, f.y, acc[0].y);
                f = __half22float2(h01); acc[1].x = fmaf(vi0, f.x, acc[1].x); acc[1].y = fmaf(vi0, f.y, acc[1].y);
                f = __half22float2(h02); acc[2].x = fmaf(vi0, f.x, acc[2].x); acc[2].y = fmaf(vi0, f.y, acc[2].y);
                f = __half22float2(h03); acc[3].x = fmaf(vi0, f.x, acc[3].x); acc[3].y = fmaf(vi0, f.y, acc[3].y);
                f = __half22float2(h10); acc[0].x = fmaf(vi1, f.x, acc[0].x); acc[0].y = fmaf(vi1, f.y, acc[0].y);
                f = __half22float2(h11); acc[1].x = fmaf(vi1, f.x, acc[1].x); acc[1].y = fmaf(vi1, f.y, acc[1].y);
                f = __half22float2(h12); acc[2].x = fmaf(vi1, f.x, acc[2].x); acc[2].y = fmaf(vi1, f.y, acc[2].y);
                f = __half22float2(h13); acc[3].x = fmaf(vi1, f.x, acc[3].x); acc[3].y = fmaf(vi1, f.y, acc[3].y);
            }
            if (i < nc) {
                int   ci = __shfl_sync(0xffffffffu, cur.x, i);
                float vi = __int_as_float(__shfl_sync(0xffffffffu, cur.y, i));
                const __half2* src = pre + (size_t)ci * 32 + lane;
#pragma unroll
                for (int b = 0; b < 4; b++) {
                    float2 f = __half22float2(__ldg(src + (size_t)b * bstride));
                    acc[b].x = fmaf(vi, f.x, acc[b].x);
                    acc[b].y = fmaf(vi, f.y, acc[b].y);
                }
            }
        }
    }

    float2* outv = (float2*)out;
#pragma unroll
    for (int b = 0; b < 4; b++) {
        float2 o;
        o.x = fmaxf(acc[b].x, 0.f);
        o.y = fmaxf(acc[b].y, 0.f);
        outv[((size_t)b * N_ + row) * 32 + lane] = o;
    }
}

extern "C" void kernel_launch(void* const* d_in, const int* in_sizes, int n_in,
                              void* d_out, int out_size) {
    const float* x     = (const float*)d_in[0];
    const int*   rows1 = (const int*)  d_in[1];
    const int*   cols1 = (const int*)  d_in[2];
    const float* vals1 = (const float*)d_in[3];
    const int*   rows2 = (const int*)  d_in[4];
    const int*   cols2 = (const int*)  d_in[5];
    const float* vals2 = (const float*)d_in[6];
    const float* W1    = (const float*)d_in[7];
    const float* W2    = (const float*)d_in[8];
    const float* bias  = (const float*)d_in[9];
    float*       out   = (float*)d_out;

    zero_kernel<<<(N2P_ / 4 + 255) / 256, 256>>>();
    hist_kernel<<<(E2_ + 255) / 256, 256>>>(rows1, rows2);
    scan_kernel<<<1, SCAN_THREADS>>>();
    fill_kernel<<<(E2_ + 255) / 256, 256>>>(rows1, cols1, vals1, rows2, cols2, vals2);
    gemm_kernel<<<ROWS_TOTAL / 32, 256>>>(x, W1, W2);
    gather_kernel<<<(N_ * 32 + 255) / 256, 256>>>(bias, out);
}

// round 7
// speedup vs baseline: 1.0415x; 1.0415x over previous
#include <cuda_runtime.h>
#include <cuda_fp16.h>
#include <cstdint>

#define B_   4
#define N_   50000
#define F_   64
#define E_   800000
#define ROWS_TOTAL (B_ * N_)          // 200000
#define E2_  (2 * E_)                 // 1600000
#define N2_  (2 * N_)                 // 100000

// ---------------------------------------------------------------------------
// Static device scratch (R3 layout)
// ---------------------------------------------------------------------------
// pre-activations in fp16, [support][b*N+n][32 half2]  (51.2 MB total)
__device__ __half2 g_preh[2ull * ROWS_TOTAL * 32];
__device__ int     g_count[N2_];      // per (support,row) degree
__device__ int     g_cursor[N2_];     // fill cursors
__device__ int     g_offs[N2_];       // exclusive prefix (CSR row offsets)
__device__ int     g_btot[128];       // scan block totals
__device__ int     g_csr_col[E2_];
__device__ float   g_csr_val[E2_];

// ---------------------------------------------------------------------------
// zero counters
// ---------------------------------------------------------------------------
__global__ void zero_kernel() {
    int i = blockIdx.x * blockDim.x + threadIdx.x;
    if (i < N2_) { g_count[i] = 0; g_cursor[i] = 0; }
}

// ---------------------------------------------------------------------------
// histogram of destination rows, both supports
// ---------------------------------------------------------------------------
__global__ __launch_bounds__(256) void hist_kernel(const int* __restrict__ rows1,
                                                   const int* __restrict__ rows2) {
    int t = blockIdx.x * blockDim.x + threadIdx.x;
    if (t >= E2_) return;
    int r = (t < E_) ? __ldg(rows1 + t) : __ldg(rows2 + (t - E_));
    int idx = (t < E_) ? r : (N_ + r);
    atomicAdd(&g_count[idx], 1);
}

// ---------------------------------------------------------------------------
// exclusive scan of g_count (100000 ints) -> g_offs, 2-level (R3 version)
// ---------------------------------------------------------------------------
__global__ __launch_bounds__(256) void scan_blocks_kernel() {
    __shared__ int sm[256];
    int base = blockIdx.x * 1024 + threadIdx.x * 4;
    int v[4];
#pragma unroll
    for (int j = 0; j < 4; j++) v[j] = (base + j < N2_) ? g_count[base + j] : 0;
    int t = v[0] + v[1] + v[2] + v[3];
    sm[threadIdx.x] = t;
    __syncthreads();
#pragma unroll
    for (int off = 1; off < 256; off <<= 1) {
        int add = (threadIdx.x >= off) ? sm[threadIdx.x - off] : 0;
        __syncthreads();
        sm[threadIdx.x] += add;
        __syncthreads();
    }
    int run = sm[threadIdx.x] - t;
#pragma unroll
    for (int j = 0; j < 4; j++) {
        if (base + j < N2_) g_offs[base + j] = run;
        run += v[j];
    }
    if (threadIdx.x == 255) g_btot[blockIdx.x] = sm[255];
}

__global__ void scan_tops_kernel(int nblk) {
    __shared__ int sm[128];
    int t = (threadIdx.x < nblk) ? g_btot[threadIdx.x] : 0;
    sm[threadIdx.x] = t;
    __syncthreads();
#pragma unroll
    for (int off = 1; off < 128; off <<= 1) {
        int add = (threadIdx.x >= off) ? sm[threadIdx.x - off] : 0;
        __syncthreads();
        sm[threadIdx.x] += add;
        __syncthreads();
    }
    if (threadIdx.x < nblk) g_btot[threadIdx.x] = sm[threadIdx.x] - t;
}

__global__ void scan_apply_kernel() {
    int i = blockIdx.x * blockDim.x + threadIdx.x;
    if (i < N2_) g_offs[i] += g_btot[i >> 10];
}

// ---------------------------------------------------------------------------
// scatter edges into CSR slots (R3 version: separate col/val arrays)
// ---------------------------------------------------------------------------
__global__ __launch_bounds__(256) void fill_kernel(const int* __restrict__ rows1,
                                                   const int* __restrict__ cols1,
                                                   const float* __restrict__ vals1,
                                                   const int* __restrict__ rows2,
                                                   const int* __restrict__ cols2,
                                                   const float* __restrict__ vals2) {
    int t = blockIdx.x * blockDim.x + threadIdx.x;
    if (t >= E2_) return;
    int r, c; float v; int idx;
    if (t < E_) {
        r = __ldg(rows1 + t); c = __ldg(cols1 + t); v = __ldg(vals1 + t);
        idx = r;
    } else {
        int e = t - E_;
        r = __ldg(rows2 + e); c = __ldg(cols2 + e); v = __ldg(vals2 + e);
        idx = N_ + r;
    }
    int slot = g_offs[idx] + atomicAdd(&g_cursor[idx], 1);
    g_csr_col[slot] = c;
    g_csr_val[slot] = v;
}

// ---------------------------------------------------------------------------
// pre1 = x@W1, pre2 = x@W2 with packed fma.rn.f32x2, store fp16 (R3 verbatim).
// ---------------------------------------------------------------------------
__global__ __launch_bounds__(256) void gemm_kernel(const float* __restrict__ x,
                                                   const float* __restrict__ W1,
                                                   const float* __restrict__ W2) {
    __shared__ float W1s[64 * 64];
    __shared__ float W2s[64 * 64];
    __shared__ float xs[64][33];

    int tid = threadIdx.x;
    for (int i = tid; i < 64 * 64; i += 256) {
        W1s[i] = W1[i];
        W2s[i] = W2[i];
    }
    int row0 = blockIdx.x * 32;
    const float4* xg = (const float4*)(x + (size_t)row0 * F_);
    for (int i = tid; i < 512; i += 256) {
        float4 v = xg[i];
        int r = i >> 4;
        int k = (i & 15) * 4;
        xs[k][r] = v.x; xs[k + 1][r] = v.y; xs[k + 2][r] = v.z; xs[k + 3][r] = v.w;
    }
    __syncthreads();

    int fpair = tid & 31;
    int rg    = tid >> 5;

    unsigned long long a1[4] = {0ull, 0ull, 0ull, 0ull};
    unsigned long long a2[4] = {0ull, 0ull, 0ull, 0ull};

#pragma unroll
    for (int k = 0; k < 64; k++) {
        unsigned long long w1p = *(const unsigned long long*)&W1s[k * 64 + fpair * 2];
        unsigned long long w2p = *(const unsigned long long*)&W2s[k * 64 + fpair * 2];
#pragma unroll
        for (int r = 0; r < 4; r++) {
            float xv = xs[k][rg * 4 + r];
            unsigned long long xp;
            asm("mov.b64 %0, {%1, %1};" : "=l"(xp) : "f"(xv));
            asm("fma.rn.f32x2 %0, %1, %2, %0;" : "+l"(a1[r]) : "l"(xp), "l"(w1p));
            asm("fma.rn.f32x2 %0, %1, %2, %0;" : "+l"(a2[r]) : "l"(xp), "l"(w2p));
        }
    }

    const size_t sup_stride = (size_t)ROWS_TOTAL * 32;
#pragma unroll
    for (int r = 0; r < 4; r++) {
        size_t row = (size_t)(row0 + rg * 4 + r);
        float lo, hi;
        asm("mov.b64 {%0, %1}, %2;" : "=f"(lo), "=f"(hi) : "l"(a1[r]));
        g_preh[row * 32 + fpair] = __floats2half2_rn(lo, hi);
        asm("mov.b64 {%0, %1}, %2;" : "=f"(lo), "=f"(hi) : "l"(a2[r]));
        g_preh[sup_stride + row * 32 + fpair] = __floats2half2_rn(lo, hi);
    }
}

// ---------------------------------------------------------------------------
// Gather SpMM + bias + relu. One warp per row; each HALF-WARP owns one edge.
// lane = (half = lane>>4, fq = lane&15); fq = 4-feature chunk (2 half2 = 8B).
// Per edge pair: 2 SHFL + 4 LDG.64 (one per batch, both edges at once).
// Cross-half partial sums merged with shfl_xor(16) at the end.
// ---------------------------------------------------------------------------
__global__ __launch_bounds__(256) void gather_kernel(const float* __restrict__ bias,
                                                     float* __restrict__ out) {
    int row  = (blockIdx.x * blockDim.x + threadIdx.x) >> 5;
    int lane = threadIdx.x & 31;
    if (row >= N_) return;
    int half = lane >> 4;
    int fq   = lane & 15;          // features fq*4 .. fq*4+3

    float4 acc[4];
#pragma unroll
    for (int b = 0; b < 4; b++) acc[b] = make_float4(0.f, 0.f, 0.f, 0.f);

    const size_t sup_stride = (size_t)ROWS_TOTAL * 32;   // half2 units
    const size_t bstride    = (size_t)N_ * 32;           // half2 units

#pragma unroll
    for (int s = 0; s < 2; s++) {
        int idx   = s * N_ + row;
        int start = g_offs[idx];
        int deg   = g_count[idx];
        const __half2* pre = g_preh + (size_t)s * sup_stride;

        for (int c0 = 0; c0 < deg; c0 += 32) {
            int nc = min(32, deg - c0);
            int   colv = 0;
            float vv   = 0.f;
            if (lane < nc) {
                colv = g_csr_col[start + c0 + lane];
                vv   = g_csr_val[start + c0 + lane];
            }
            int i = 0;
            for (; i + 2 <= nc; i += 2) {
                int   ci = __shfl_sync(0xffffffffu, colv, i + half);
                float vi = __shfl_sync(0xffffffffu, vv,   i + half);
                const __half2* p = pre + (size_t)ci * 32 + fq * 2;
                uint2 h0 = __ldg((const uint2*)(p));
                uint2 h1 = __ldg((const uint2*)(p + bstride));
                uint2 h2 = __ldg((const uint2*)(p + 2 * bstride));
                uint2 h3 = __ldg((const uint2*)(p + 3 * bstride));
                float2 fa, fb;
                fa = __half22float2(*(const __half2*)&h0.x);
                fb = __half22float2(*(const __half2*)&h0.y);
                acc[0].x = fmaf(vi, fa.x, acc[0].x); acc[0].y = fmaf(vi, fa.y, acc[0].y);
                acc[0].z = fmaf(vi, fb.x, acc[0].z); acc[0].w = fmaf(vi, fb.y, acc[0].w);
                fa = __half22float2(*(const __half2*)&h1.x);
                fb = __half22float2(*(const __half2*)&h1.y);
                acc[1].x = fmaf(vi, fa.x, acc[1].x); acc[1].y = fmaf(vi, fa.y, acc[1].y);
                acc[1].z = fmaf(vi, fb.x, acc[1].z); acc[1].w = fmaf(vi, fb.y, acc[1].w);
                fa = __half22float2(*(const __half2*)&h2.x);
                fb = __half22float2(*(const __half2*)&h2.y);
                acc[2].x = fmaf(vi, fa.x, acc[2].x); acc[2].y = fmaf(vi, fa.y, acc[2].y);
                acc[2].z = fmaf(vi, fb.x, acc[2].z); acc[2].w = fmaf(vi, fb.y, acc[2].w);
                fa = __half22float2(*(const __half2*)&h3.x);
                fb = __half22float2(*(const __half2*)&h3.y);
                acc[3].x = fmaf(vi, fa.x, acc[3].x); acc[3].y = fmaf(vi, fa.y, acc[3].y);
                acc[3].z = fmaf(vi, fb.x, acc[3].z); acc[3].w = fmaf(vi, fb.y, acc[3].w);
            }
            if (i < nc) {   // odd remainder: half 0 only
                int   ci = __shfl_sync(0xffffffffu, colv, i);
                float vi = __shfl_sync(0xffffffffu, vv,   i);
                if (half == 0) {
                    const __half2* p = pre + (size_t)ci * 32 + fq * 2;
#pragma unroll
                    for (int b = 0; b < 4; b++) {
                        uint2 h = __ldg((const uint2*)(p + (size_t)b * bstride));
                        float2 fa = __half22float2(*(const __half2*)&h.x);
                        float2 fb = __half22float2(*(const __half2*)&h.y);
                        acc[b].x = fmaf(vi, fa.x, acc[b].x);
                        acc[b].y = fmaf(vi, fa.y, acc[b].y);
                        acc[b].z = fmaf(vi, fb.x, acc[b].z);
                        acc[b].w = fmaf(vi, fb.y, acc[b].w);
                    }
                }
            }
        }
    }

    // merge the two half-warp edge subsets
#pragma unroll
    for (int b = 0; b < 4; b++) {
        acc[b].x += __shfl_xor_sync(0xffffffffu, acc[b].x, 16);
        acc[b].y += __shfl_xor_sync(0xffffffffu, acc[b].y, 16);
        acc[b].z += __shfl_xor_sync(0xffffffffu, acc[b].z, 16);
        acc[b].w += __shfl_xor_sync(0xffffffffu, acc[b].w, 16);
    }

    // bias + relu + store: half h writes batches 2h, 2h+1 (float4 per lane)
    float4 bv = *(const float4*)(bias + fq * 4);
#pragma unroll
    for (int j = 0; j < 2; j++) {
        int b = half * 2 + j;
        float4 o;
        o.x = fmaxf(acc[b].x + bv.x, 0.f);
        o.y = fmaxf(acc[b].y + bv.y, 0.f);
        o.z = fmaxf(acc[b].z + bv.z, 0.f);
        o.w = fmaxf(acc[b].w + bv.w, 0.f);
        *(float4*)(out + ((size_t)b * N_ + row) * F_ + fq * 4) = o;
    }
}

extern "C" void kernel_launch(void* const* d_in, const int* in_sizes, int n_in,
                              void* d_out, int out_size) {
    const float* x     = (const float*)d_in[0];
    const int*   rows1 = (const int*)  d_in[1];
    const int*   cols1 = (const int*)  d_in[2];
    const float* vals1 = (const float*)d_in[3];
    const int*   rows2 = (const int*)  d_in[4];
    const int*   cols2 = (const int*)  d_in[5];
    const float* vals2 = (const float*)d_in[6];
    const float* W1    = (const float*)d_in[7];
    const float* W2    = (const float*)d_in[8];
    const float* bias  = (const float*)d_in[9];
    float*       out   = (float*)d_out;

    const int nScanBlocks = (N2_ + 1023) / 1024;   // 98

    zero_kernel<<<(N2_ + 255) / 256, 256>>>();
    hist_kernel<<<(E2_ + 255) / 256, 256>>>(rows1, rows2);
    scan_blocks_kernel<<<nScanBlocks, 256>>>();
    scan_tops_kernel<<<1, 128>>>(nScanBlocks);
    scan_apply_kernel<<<(N2_ + 255) / 256, 256>>>();
    fill_kernel<<<(E2_ + 255) / 256, 256>>>(rows1, cols1, vals1, rows2, cols2, vals2);

    gemm_kernel<<<ROWS_TOTAL / 32, 256>>>(x, W1, W2);
    gather_kernel<<<(N_ * 32 + 255) / 256, 256>>>(bias, out);
}